// round 1
// baseline (speedup 1.0000x reference)
#include <cuda_runtime.h>
#include <math.h>

#define S_LEN 2048
#define HIDDEN 6144
#define HD 128
#define NKVH 8
#define NG 6
#define NH 48

// Scratch (device globals — no allocation allowed in kernel_launch)
__device__ float g_qkv[33554432];   // [2,2048,8,8,128] = 128 MB
__device__ float g_ctx[25165824];   // [2,2048,48,128]  = 100 MB

// ---------------------------------------------------------------------------
// GEMM: C[M,N] = A[M,K] * B[N,K]^T   (both A and B row-major, K-contiguous)
// 128x128 tile, BK=8, 256 threads, 8x8 per thread, prefetch double-buffer in regs
// ---------------------------------------------------------------------------
__global__ __launch_bounds__(256, 2)
void gemm_nt_kernel(const float* __restrict__ A, const float* __restrict__ B,
                    float* __restrict__ C, int M, int N, int K) {
    __shared__ float As[8][128];
    __shared__ float Bs[8][128];
    const int tid = threadIdx.x;
    const int bm = blockIdx.y * 128;
    const int bn = blockIdx.x * 128;
    const int lr = tid >> 1;            // 0..127: tile row for loading
    const int lk = (tid & 1) * 4;       // 0 or 4: k offset
    const float* Ag = A + (size_t)(bm + lr) * K + lk;
    const float* Bg = B + (size_t)(bn + lr) * K + lk;
    const int ty = tid >> 4;            // 0..15
    const int tx = tid & 15;            // 0..15

    float acc[8][8];
#pragma unroll
    for (int i = 0; i < 8; i++)
#pragma unroll
        for (int j = 0; j < 8; j++) acc[i][j] = 0.f;

    float4 a4 = *(const float4*)Ag;
    float4 b4 = *(const float4*)Bg;

    for (int k0 = 0; k0 < K; k0 += 8) {
        __syncthreads();
        As[lk + 0][lr] = a4.x; As[lk + 1][lr] = a4.y;
        As[lk + 2][lr] = a4.z; As[lk + 3][lr] = a4.w;
        Bs[lk + 0][lr] = b4.x; Bs[lk + 1][lr] = b4.y;
        Bs[lk + 2][lr] = b4.z; Bs[lk + 3][lr] = b4.w;
        __syncthreads();
        if (k0 + 8 < K) {
            a4 = *(const float4*)(Ag + k0 + 8);
            b4 = *(const float4*)(Bg + k0 + 8);
        }
#pragma unroll
        for (int kk = 0; kk < 8; kk++) {
            float4 av0 = *(const float4*)&As[kk][ty * 8];
            float4 av1 = *(const float4*)&As[kk][ty * 8 + 4];
            float4 bv0 = *(const float4*)&Bs[kk][tx * 4];        // cols 4tx..4tx+3
            float4 bv1 = *(const float4*)&Bs[kk][64 + tx * 4];   // cols 64+4tx..
            float a[8] = {av0.x, av0.y, av0.z, av0.w, av1.x, av1.y, av1.z, av1.w};
            float b[8] = {bv0.x, bv0.y, bv0.z, bv0.w, bv1.x, bv1.y, bv1.z, bv1.w};
#pragma unroll
            for (int i = 0; i < 8; i++)
#pragma unroll
                for (int j = 0; j < 8; j++) acc[i][j] += a[i] * b[j];
        }
    }

#pragma unroll
    for (int i = 0; i < 8; i++) {
        int row = bm + ty * 8 + i;
        float4 c0 = make_float4(acc[i][0], acc[i][1], acc[i][2], acc[i][3]);
        float4 c1 = make_float4(acc[i][4], acc[i][5], acc[i][6], acc[i][7]);
        *(float4*)&C[(size_t)row * N + bn + tx * 4] = c0;
        *(float4*)&C[(size_t)row * N + bn + 64 + tx * 4] = c1;
    }
}

// ---------------------------------------------------------------------------
// RoPE in-place on q heads (slots 0..5) and k (slot 6) of qkv [B,S,KVH,8,D]
// dims paired (i, i+64), freq = s * theta^(-i/64)
// ---------------------------------------------------------------------------
__global__ void rope_kernel(float* __restrict__ qkv) {
    int idx = blockIdx.x * blockDim.x + threadIdx.x;
    if (idx >= 4096 * 8 * 7 * 64) return;
    int i = idx & 63;
    int t = idx >> 6;
    int slot = t % 7;
    t /= 7;
    int kvh = t & 7;
    int bs = t >> 3;
    int s = bs & (S_LEN - 1);
    // inv_freq = 1e6^(-i/64); log2(1e6) = 19.931568569324174
    float inv = exp2f(-(float)i * (19.931568569324174f / 64.0f));
    float f = (float)s * inv;
    float c = cosf(f), sn = sinf(f);
    float* p = qkv + (((size_t)bs * NKVH + kvh) * 8 + slot) * HD;
    float a = p[i], b = p[i + 64];
    p[i]      = a * c - b * sn;
    p[i + 64] = b * c + a * sn;
}

// ---------------------------------------------------------------------------
// Flash attention, causal, GQA. One block = (b, h, q-tile of 64).
// 256 threads as 16x16. Thread (ty,tx): score rows r=ty*4+ii, cols c=tx+16*jj.
// Output cols d = {4tx..4tx+3, 64+4tx..64+4tx+3}.
// ---------------------------------------------------------------------------
#define BQ 64
#define BK 64
#define QPAD 132
#define KPAD 132

__global__ __launch_bounds__(256, 1)
void attn_kernel(const float* __restrict__ qkv, float* __restrict__ ctx) {
    extern __shared__ float sm[];
    float* Qs = sm;                       // [64][132]
    float* Ks = Qs + BQ * QPAD;           // [64][132]
    float* Vs = Ks + BK * KPAD;           // [64][128]
    float* Ss = Vs + BK * HD;             // [64][64]

    const int tid = threadIdx.x;
    const int qt = blockIdx.x;
    const int h  = blockIdx.y;
    const int b  = blockIdx.z;
    const int kvh  = h / NG;
    const int slot = h % NG;
    const int ty = tid >> 4;
    const int tx = tid & 15;

    const float scale = 0.08838834764831845f;  // 1/sqrt(128)
    const size_t base_bs = (size_t)b * S_LEN;

    // Load Q tile, pre-scaled
    {
        const int i0 = tid >> 5;
        const int d4 = tid & 31;
#pragma unroll
        for (int it = 0; it < 8; it++) {
            int i = i0 + it * 8;
            int s = qt * BQ + i;
            const float* g = qkv + (((base_bs + s) * NKVH + kvh) * 8 + slot) * HD + 4 * d4;
            float4 v = *(const float4*)g;
            float* dst = &Qs[i * QPAD + 4 * d4];
            dst[0] = v.x * scale; dst[1] = v.y * scale;
            dst[2] = v.z * scale; dst[3] = v.w * scale;
        }
    }

    float m[4], l[4], o[4][8];
#pragma unroll
    for (int ii = 0; ii < 4; ii++) {
        m[ii] = -INFINITY; l[ii] = 0.f;
#pragma unroll
        for (int k = 0; k < 8; k++) o[ii][k] = 0.f;
    }

    for (int kt = 0; kt <= qt; kt++) {
        __syncthreads();  // protect Ks/Vs/Ss reuse (and Qs on first iter)
        // Load K, V tiles
        {
            const int i0 = tid >> 5;
            const int d4 = tid & 31;
#pragma unroll
            for (int it = 0; it < 8; it++) {
                int j = i0 + it * 8;
                int s = kt * BK + j;
                const float* gk = qkv + (((base_bs + s) * NKVH + kvh) * 8 + NG) * HD + 4 * d4;
                const float* gv = qkv + (((base_bs + s) * NKVH + kvh) * 8 + NG + 1) * HD + 4 * d4;
                *(float4*)&Ks[j * KPAD + 4 * d4] = *(const float4*)gk;
                *(float4*)&Vs[j * HD   + 4 * d4] = *(const float4*)gv;
            }
        }
        __syncthreads();

        // Scores: sc[ii][jj] = Q[r] . K[c],  r = ty*4+ii, c = tx+16*jj
        float sc[4][4];
#pragma unroll
        for (int ii = 0; ii < 4; ii++)
#pragma unroll
            for (int jj = 0; jj < 4; jj++) sc[ii][jj] = 0.f;

        for (int d4 = 0; d4 < 32; d4++) {
            float qv[4][4], kv[4][4];
#pragma unroll
            for (int ii = 0; ii < 4; ii++) {
                float4 q = *(const float4*)&Qs[(ty * 4 + ii) * QPAD + 4 * d4];
                qv[ii][0] = q.x; qv[ii][1] = q.y; qv[ii][2] = q.z; qv[ii][3] = q.w;
            }
#pragma unroll
            for (int jj = 0; jj < 4; jj++) {
                float4 k = *(const float4*)&Ks[(tx + 16 * jj) * KPAD + 4 * d4];
                kv[jj][0] = k.x; kv[jj][1] = k.y; kv[jj][2] = k.z; kv[jj][3] = k.w;
            }
#pragma unroll
            for (int dd = 0; dd < 4; dd++)
#pragma unroll
                for (int ii = 0; ii < 4; ii++)
#pragma unroll
                    for (int jj = 0; jj < 4; jj++)
                        sc[ii][jj] += qv[ii][dd] * kv[jj][dd];
        }

        // Causal mask (diagonal tile only)
        if (kt == qt) {
#pragma unroll
            for (int ii = 0; ii < 4; ii++)
#pragma unroll
                for (int jj = 0; jj < 4; jj++) {
                    int r = ty * 4 + ii, c = tx + 16 * jj;
                    if (c > r) sc[ii][jj] = -1e30f;
                }
        }

        // Online softmax update per row
#pragma unroll
        for (int ii = 0; ii < 4; ii++) {
            float rmax = fmaxf(fmaxf(sc[ii][0], sc[ii][1]), fmaxf(sc[ii][2], sc[ii][3]));
#pragma unroll
            for (int msk = 1; msk < 16; msk <<= 1)
                rmax = fmaxf(rmax, __shfl_xor_sync(0xffffffffu, rmax, msk));
            float mnew = fmaxf(m[ii], rmax);
            float alpha = expf(m[ii] - mnew);
            float p0 = expf(sc[ii][0] - mnew);
            float p1 = expf(sc[ii][1] - mnew);
            float p2 = expf(sc[ii][2] - mnew);
            float p3 = expf(sc[ii][3] - mnew);
            float rsum = p0 + p1 + p2 + p3;
#pragma unroll
            for (int msk = 1; msk < 16; msk <<= 1)
                rsum += __shfl_xor_sync(0xffffffffu, rsum, msk);
            l[ii] = l[ii] * alpha + rsum;
            m[ii] = mnew;
#pragma unroll
            for (int k = 0; k < 8; k++) o[ii][k] *= alpha;
            int r = ty * 4 + ii;
            Ss[r * 64 + tx]      = p0;
            Ss[r * 64 + tx + 16] = p1;
            Ss[r * 64 + tx + 32] = p2;
            Ss[r * 64 + tx + 48] = p3;
        }
        __syncthreads();

        // PV: o[ii][*] += P[r][j] * V[j][*]
#pragma unroll 4
        for (int j = 0; j < BK; j++) {
            float4 v0 = *(const float4*)&Vs[j * HD + 4 * tx];
            float4 v1 = *(const float4*)&Vs[j * HD + 64 + 4 * tx];
            float pr[4];
#pragma unroll
            for (int ii = 0; ii < 4; ii++) pr[ii] = Ss[(ty * 4 + ii) * 64 + j];
#pragma unroll
            for (int ii = 0; ii < 4; ii++) {
                o[ii][0] += pr[ii] * v0.x; o[ii][1] += pr[ii] * v0.y;
                o[ii][2] += pr[ii] * v0.z; o[ii][3] += pr[ii] * v0.w;
                o[ii][4] += pr[ii] * v1.x; o[ii][5] += pr[ii] * v1.y;
                o[ii][6] += pr[ii] * v1.z; o[ii][7] += pr[ii] * v1.w;
            }
        }
    }

    // Epilogue: normalize and write ctx[b, s, h, d]
#pragma unroll
    for (int ii = 0; ii < 4; ii++) {
        float inv_l = 1.0f / l[ii];
        int s = qt * BQ + ty * 4 + ii;
        float* dst = ctx + (base_bs + s) * (size_t)HIDDEN + h * HD;
        float4 c0 = make_float4(o[ii][0] * inv_l, o[ii][1] * inv_l,
                                o[ii][2] * inv_l, o[ii][3] * inv_l);
        float4 c1 = make_float4(o[ii][4] * inv_l, o[ii][5] * inv_l,
                                o[ii][6] * inv_l, o[ii][7] * inv_l);
        *(float4*)&dst[4 * tx] = c0;
        *(float4*)&dst[64 + 4 * tx] = c1;
    }
}

// ---------------------------------------------------------------------------
extern "C" void kernel_launch(void* const* d_in, const int* in_sizes, int n_in,
                              void* d_out, int out_size) {
    const float* x    = (const float*)d_in[0];   // [2,2048,6144]
    const float* Wqkv = (const float*)d_in[1];   // [8192,6144]
    const float* Wo   = (const float*)d_in[2];   // [6144,6144]
    float* out = (float*)d_out;                  // [2,2048,6144]

    float* qkv = nullptr;
    float* ctx = nullptr;
    cudaGetSymbolAddress((void**)&qkv, g_qkv);
    cudaGetSymbolAddress((void**)&ctx, g_ctx);

    // 1) QKV projection: [4096,8192] = X[4096,6144] @ Wqkv[8192,6144]^T
    gemm_nt_kernel<<<dim3(8192 / 128, 4096 / 128), 256>>>(x, Wqkv, qkv, 4096, 8192, 6144);

    // 2) RoPE in place on q heads + k
    rope_kernel<<<(4096 * 8 * 7 * 64) / 256, 256>>>(qkv);

    // 3) Flash attention -> ctx [2,2048,48,128]
    const int attn_smem = (BQ * QPAD + BK * KPAD + BK * HD + BQ * BK) * sizeof(float);
    cudaFuncSetAttribute(attn_kernel, cudaFuncAttributeMaxDynamicSharedMemorySize, attn_smem);
    attn_kernel<<<dim3(32, NH, 2), 256, attn_smem>>>(qkv, ctx);

    // 4) Output projection: [4096,6144] = ctx[4096,6144] @ Wo[6144,6144]^T
    gemm_nt_kernel<<<dim3(6144 / 128, 4096 / 128), 256>>>(ctx, Wo, out, 4096, 6144, 6144);
}

// round 3
// speedup vs baseline: 1.5245x; 1.5245x over previous
#include <cuda_runtime.h>
#include <cuda_bf16.h>
#include <math.h>
#include <stdint.h>

#define S_LEN 2048
#define HIDDEN 6144
#define HD 128
#define NKVH 8
#define NG 6
#define NH 48

// bf16x3 split-K GEMM config
#define K3 (3 * HIDDEN)          // 18432
#define NCH (K3 / 32)            // 576 BK=32 chunks
#define PITCHW 20                // smem row pitch in 32-bit words (40 bf16 = 80B)

typedef unsigned int u32;

// ---------------------------------------------------------------------------
// Device scratch (no allocation allowed at runtime)
// ---------------------------------------------------------------------------
__device__ float g_qkv[33554432];                 // [2,2048,8,8,128] fp32
__device__ float g_ctx[25165824];                 // [2,2048,48,128]  fp32
__device__ __nv_bfloat16 g_a3x[75497472];         // [4096, 18432]
__device__ __nv_bfloat16 g_wqkv3[150994944];      // [8192, 18432]
__device__ __nv_bfloat16 g_wo3[113246208];        // [6144, 18432]
__device__ __nv_bfloat16 g_ctx3[75497472];        // [4096, 18432]

__device__ __forceinline__ u32 smem_u32(const void* p) {
    u32 a;
    asm("{ .reg .u64 t; cvta.to.shared.u64 t, %1; cvt.u32.u64 %0, t; }" : "=r"(a) : "l"(p));
    return a;
}

#define CP16(d, s) \
    asm volatile("cp.async.cg.shared.global [%0], [%1], 16;" :: "r"(d), "l"(s))

__device__ __forceinline__ void mma16816(float* c, const u32* a, const u32* b) {
    asm volatile(
        "mma.sync.aligned.m16n8k16.row.col.f32.bf16.bf16.f32 "
        "{%0,%1,%2,%3}, {%4,%5,%6,%7}, {%8,%9}, {%0,%1,%2,%3};"
        : "+f"(c[0]), "+f"(c[1]), "+f"(c[2]), "+f"(c[3])
        : "r"(a[0]), "r"(a[1]), "r"(a[2]), "r"(a[3]), "r"(b[0]), "r"(b[1]));
}

// ---------------------------------------------------------------------------
// Split fp32 -> bf16 (hi, lo): [hi|hi|lo] (left operand) / [hi|lo|hi] (right)
// ---------------------------------------------------------------------------
__global__ void split3_kernel(const float* __restrict__ in,
                              __nv_bfloat16* __restrict__ out,
                              int total4, int is_right) {
    int idx = blockIdx.x * blockDim.x + threadIdx.x;
    if (idx >= total4) return;
    float4 v = ((const float4*)in)[idx];
    int r = idx / (HIDDEN / 4);
    int c = (idx % (HIDDEN / 4)) * 4;
    float vv[4] = {v.x, v.y, v.z, v.w};
    unsigned hs[4], ls[4];
#pragma unroll
    for (int j = 0; j < 4; j++) {
        __nv_bfloat16 h = __float2bfloat16(vv[j]);
        __nv_bfloat16 l = __float2bfloat16(vv[j] - __bfloat162float(h));
        hs[j] = __bfloat16_as_ushort(h);
        ls[j] = __bfloat16_as_ushort(l);
    }
    uint2 hp = make_uint2(hs[0] | (hs[1] << 16), hs[2] | (hs[3] << 16));
    uint2 lp = make_uint2(ls[0] | (ls[1] << 16), ls[2] | (ls[3] << 16));
    __nv_bfloat16* row = out + (size_t)r * K3 + c;
    *(uint2*)row = hp;
    *(uint2*)(row + HIDDEN)     = is_right ? lp : hp;
    *(uint2*)(row + 2 * HIDDEN) = is_right ? hp : lp;
}

// ---------------------------------------------------------------------------
// bf16 HMMA GEMM: C[M,Ntot](fp32) = A[M,K3](bf16) * B[Ntot,K3](bf16)^T
// CTA tile 128x128, BK=32, 8 warps (64x32 each), cp.async double buffer.
// ---------------------------------------------------------------------------
__global__ void __launch_bounds__(256, 2)
gemm_mma_kernel(const __nv_bfloat16* __restrict__ A,
                const __nv_bfloat16* __restrict__ B,
                float* __restrict__ C, int NT, int Ntot) {
    __shared__ __align__(16) u32 Asm[2][128 * PITCHW];
    __shared__ __align__(16) u32 Bsm[2][128 * PITCHW];

    const int tid  = threadIdx.x;
    const int lane = tid & 31;
    const int wid  = tid >> 5;
    const int wm   = wid >> 2;          // 0..1
    const int wn   = wid & 3;           // 0..3
    const int lr   = lane >> 2;         // 0..7
    const int lq   = lane & 3;          // 0..3

    // L2-friendly rasterization: groups of 8 m-tiles per n sweep
    int bid = blockIdx.x;
    int gsz = 8 * NT;
    int g = bid / gsz, r = bid % gsz;
    int mt = g * 8 + (r & 7);
    int nt = r >> 3;
    int bm = mt * 128, bn = nt * 128;

    // global load mapping: thread -> rows (tid>>2, tid>>2 + 64), 16B chunk tid&3
    const int grow = tid >> 2;
    const int gc16 = tid & 3;
    const __nv_bfloat16* Ag = A + (size_t)(bm + grow) * K3 + gc16 * 8;
    const __nv_bfloat16* Bg = B + (size_t)(bn + grow) * K3 + gc16 * 8;
    const u32 sA0 = smem_u32(&Asm[0][0]);
    const u32 sB0 = smem_u32(&Bsm[0][0]);
    const u32 doff = (u32)(grow * PITCHW + gc16 * 4) * 4;
    const u32 doff2 = doff + 64 * PITCHW * 4;
    const u32 bufstride = 128 * PITCHW * 4;

    float acc[4][4][4];
#pragma unroll
    for (int mi = 0; mi < 4; mi++)
#pragma unroll
        for (int ni = 0; ni < 4; ni++)
#pragma unroll
            for (int q = 0; q < 4; q++) acc[mi][ni][q] = 0.f;

    // prefetch chunk 0 into buf 0
    {
        CP16(sA0 + doff,  Ag);
        CP16(sA0 + doff2, Ag + (size_t)64 * K3);
        CP16(sB0 + doff,  Bg);
        CP16(sB0 + doff2, Bg + (size_t)64 * K3);
        asm volatile("cp.async.commit_group;");
    }

    for (int c = 0; c < NCH; c++) {
        if (c + 1 < NCH) {
            u32 nb = (u32)((c + 1) & 1) * bufstride;
            const __nv_bfloat16* ga = Ag + (c + 1) * 32;
            const __nv_bfloat16* gb = Bg + (c + 1) * 32;
            CP16(sA0 + nb + doff,  ga);
            CP16(sA0 + nb + doff2, ga + (size_t)64 * K3);
            CP16(sB0 + nb + doff,  gb);
            CP16(sB0 + nb + doff2, gb + (size_t)64 * K3);
            asm volatile("cp.async.commit_group;");
            asm volatile("cp.async.wait_group 1;");
        } else {
            asm volatile("cp.async.wait_group 0;");
        }
        __syncthreads();

        const u32* As = Asm[c & 1];
        const u32* Bs = Bsm[c & 1];
#pragma unroll
        for (int ks = 0; ks < 2; ks++) {
            u32 a[4][4], b[4][2];
#pragma unroll
            for (int mi = 0; mi < 4; mi++) {
                int w = (wm * 64 + mi * 16 + lr) * PITCHW + ks * 8 + lq;
                a[mi][0] = As[w];
                a[mi][1] = As[w + 8 * PITCHW];
                a[mi][2] = As[w + 4];
                a[mi][3] = As[w + 8 * PITCHW + 4];
            }
#pragma unroll
            for (int ni = 0; ni < 4; ni++) {
                int w = (wn * 32 + ni * 8 + lr) * PITCHW + ks * 8 + lq;
                b[ni][0] = Bs[w];
                b[ni][1] = Bs[w + 4];
            }
#pragma unroll
            for (int mi = 0; mi < 4; mi++)
#pragma unroll
                for (int ni = 0; ni < 4; ni++)
                    mma16816(acc[mi][ni], a[mi], b[ni]);
        }
        __syncthreads();
    }

    // epilogue
#pragma unroll
    for (int mi = 0; mi < 4; mi++) {
        int row = bm + wm * 64 + mi * 16 + lr;
#pragma unroll
        for (int ni = 0; ni < 4; ni++) {
            int col = bn + wn * 32 + ni * 8 + lq * 2;
            float* p0 = C + (size_t)row * Ntot + col;
            *(float2*)p0 = make_float2(acc[mi][ni][0], acc[mi][ni][1]);
            *(float2*)(p0 + (size_t)8 * Ntot) = make_float2(acc[mi][ni][2], acc[mi][ni][3]);
        }
    }
}

// ---------------------------------------------------------------------------
// RoPE in-place on q heads (slots 0..5) and k (slot 6) of qkv [B,S,KVH,8,D]
// ---------------------------------------------------------------------------
__global__ void rope_kernel(float* __restrict__ qkv) {
    int idx = blockIdx.x * blockDim.x + threadIdx.x;
    if (idx >= 4096 * 8 * 7 * 64) return;
    int i = idx & 63;
    int t = idx >> 6;
    int slot = t % 7;
    t /= 7;
    int kvh = t & 7;
    int bs = t >> 3;
    int s = bs & (S_LEN - 1);
    float inv = exp2f(-(float)i * (19.931568569324174f / 64.0f));
    float f = (float)s * inv;
    float c = cosf(f), sn = sinf(f);
    float* p = qkv + (((size_t)bs * NKVH + kvh) * 8 + slot) * HD;
    float a = p[i], b = p[i + 64];
    p[i]      = a * c - b * sn;
    p[i + 64] = b * c + a * sn;
}

// ---------------------------------------------------------------------------
// Flash attention, causal, GQA (fp32 SIMT)
// ---------------------------------------------------------------------------
#define BQ 64
#define BK 64
#define QPAD 132
#define KPAD 132

__global__ __launch_bounds__(256, 1)
void attn_kernel(const float* __restrict__ qkv, float* __restrict__ ctx) {
    extern __shared__ float sm[];
    float* Qs = sm;
    float* Ks = Qs + BQ * QPAD;
    float* Vs = Ks + BK * KPAD;
    float* Ss = Vs + BK * HD;

    const int tid = threadIdx.x;
    const int qt = blockIdx.x;
    const int h  = blockIdx.y;
    const int b  = blockIdx.z;
    const int kvh  = h / NG;
    const int slot = h % NG;
    const int ty = tid >> 4;
    const int tx = tid & 15;

    const float scale = 0.08838834764831845f;
    const size_t base_bs = (size_t)b * S_LEN;

    {
        const int i0 = tid >> 5;
        const int d4 = tid & 31;
#pragma unroll
        for (int it = 0; it < 8; it++) {
            int i = i0 + it * 8;
            int s = qt * BQ + i;
            const float* g = qkv + (((base_bs + s) * NKVH + kvh) * 8 + slot) * HD + 4 * d4;
            float4 v = *(const float4*)g;
            float* dst = &Qs[i * QPAD + 4 * d4];
            dst[0] = v.x * scale; dst[1] = v.y * scale;
            dst[2] = v.z * scale; dst[3] = v.w * scale;
        }
    }

    float m[4], l[4], o[4][8];
#pragma unroll
    for (int ii = 0; ii < 4; ii++) {
        m[ii] = -INFINITY; l[ii] = 0.f;
#pragma unroll
        for (int k = 0; k < 8; k++) o[ii][k] = 0.f;
    }

    for (int kt = 0; kt <= qt; kt++) {
        __syncthreads();
        {
            const int i0 = tid >> 5;
            const int d4 = tid & 31;
#pragma unroll
            for (int it = 0; it < 8; it++) {
                int j = i0 + it * 8;
                int s = kt * BK + j;
                const float* gk = qkv + (((base_bs + s) * NKVH + kvh) * 8 + NG) * HD + 4 * d4;
                const float* gv = qkv + (((base_bs + s) * NKVH + kvh) * 8 + NG + 1) * HD + 4 * d4;
                *(float4*)&Ks[j * KPAD + 4 * d4] = *(const float4*)gk;
                *(float4*)&Vs[j * HD   + 4 * d4] = *(const float4*)gv;
            }
        }
        __syncthreads();

        float sc[4][4];
#pragma unroll
        for (int ii = 0; ii < 4; ii++)
#pragma unroll
            for (int jj = 0; jj < 4; jj++) sc[ii][jj] = 0.f;

        for (int d4 = 0; d4 < 32; d4++) {
            float qv[4][4], kv[4][4];
#pragma unroll
            for (int ii = 0; ii < 4; ii++) {
                float4 q = *(const float4*)&Qs[(ty * 4 + ii) * QPAD + 4 * d4];
                qv[ii][0] = q.x; qv[ii][1] = q.y; qv[ii][2] = q.z; qv[ii][3] = q.w;
            }
#pragma unroll
            for (int jj = 0; jj < 4; jj++) {
                float4 k = *(const float4*)&Ks[(tx + 16 * jj) * KPAD + 4 * d4];
                kv[jj][0] = k.x; kv[jj][1] = k.y; kv[jj][2] = k.z; kv[jj][3] = k.w;
            }
#pragma unroll
            for (int dd = 0; dd < 4; dd++)
#pragma unroll
                for (int ii = 0; ii < 4; ii++)
#pragma unroll
                    for (int jj = 0; jj < 4; jj++)
                        sc[ii][jj] += qv[ii][dd] * kv[jj][dd];
        }

        if (kt == qt) {
#pragma unroll
            for (int ii = 0; ii < 4; ii++)
#pragma unroll
                for (int jj = 0; jj < 4; jj++) {
                    int rr = ty * 4 + ii, cc = tx + 16 * jj;
                    if (cc > rr) sc[ii][jj] = -1e30f;
                }
        }

#pragma unroll
        for (int ii = 0; ii < 4; ii++) {
            float rmax = fmaxf(fmaxf(sc[ii][0], sc[ii][1]), fmaxf(sc[ii][2], sc[ii][3]));
#pragma unroll
            for (int msk = 1; msk < 16; msk <<= 1)
                rmax = fmaxf(rmax, __shfl_xor_sync(0xffffffffu, rmax, msk));
            float mnew = fmaxf(m[ii], rmax);
            float alpha = expf(m[ii] - mnew);
            float p0 = expf(sc[ii][0] - mnew);
            float p1 = expf(sc[ii][1] - mnew);
            float p2 = expf(sc[ii][2] - mnew);
            float p3 = expf(sc[ii][3] - mnew);
            float rsum = p0 + p1 + p2 + p3;
#pragma unroll
            for (int msk = 1; msk < 16; msk <<= 1)
                rsum += __shfl_xor_sync(0xffffffffu, rsum, msk);
            l[ii] = l[ii] * alpha + rsum;
            m[ii] = mnew;
#pragma unroll
            for (int k = 0; k < 8; k++) o[ii][k] *= alpha;
            int rr = ty * 4 + ii;
            Ss[rr * 64 + tx]      = p0;
            Ss[rr * 64 + tx + 16] = p1;
            Ss[rr * 64 + tx + 32] = p2;
            Ss[rr * 64 + tx + 48] = p3;
        }
        __syncthreads();

#pragma unroll 4
        for (int j = 0; j < BK; j++) {
            float4 v0 = *(const float4*)&Vs[j * HD + 4 * tx];
            float4 v1 = *(const float4*)&Vs[j * HD + 64 + 4 * tx];
            float pr[4];
#pragma unroll
            for (int ii = 0; ii < 4; ii++) pr[ii] = Ss[(ty * 4 + ii) * 64 + j];
#pragma unroll
            for (int ii = 0; ii < 4; ii++) {
                o[ii][0] += pr[ii] * v0.x; o[ii][1] += pr[ii] * v0.y;
                o[ii][2] += pr[ii] * v0.z; o[ii][3] += pr[ii] * v0.w;
                o[ii][4] += pr[ii] * v1.x; o[ii][5] += pr[ii] * v1.y;
                o[ii][6] += pr[ii] * v1.z; o[ii][7] += pr[ii] * v1.w;
            }
        }
    }

#pragma unroll
    for (int ii = 0; ii < 4; ii++) {
        float inv_l = 1.0f / l[ii];
        int s = qt * BQ + ty * 4 + ii;
        float* dst = ctx + (base_bs + s) * (size_t)HIDDEN + h * HD;
        float4 c0 = make_float4(o[ii][0] * inv_l, o[ii][1] * inv_l,
                                o[ii][2] * inv_l, o[ii][3] * inv_l);
        float4 c1 = make_float4(o[ii][4] * inv_l, o[ii][5] * inv_l,
                                o[ii][6] * inv_l, o[ii][7] * inv_l);
        *(float4*)&dst[4 * tx] = c0;
        *(float4*)&dst[64 + 4 * tx] = c1;
    }
}

// ---------------------------------------------------------------------------
extern "C" void kernel_launch(void* const* d_in, const int* in_sizes, int n_in,
                              void* d_out, int out_size) {
    const float* x    = (const float*)d_in[0];   // [2,2048,6144]
    const float* Wqkv = (const float*)d_in[1];   // [8192,6144]
    const float* Wo   = (const float*)d_in[2];   // [6144,6144]
    float* out = (float*)d_out;                  // [2,2048,6144]

    float *qkv = nullptr, *ctx = nullptr;
    __nv_bfloat16 *a3x = nullptr, *wqkv3 = nullptr, *wo3 = nullptr, *ctx3 = nullptr;
    cudaGetSymbolAddress((void**)&qkv,   g_qkv);
    cudaGetSymbolAddress((void**)&ctx,   g_ctx);
    cudaGetSymbolAddress((void**)&a3x,   g_a3x);
    cudaGetSymbolAddress((void**)&wqkv3, g_wqkv3);
    cudaGetSymbolAddress((void**)&wo3,   g_wo3);
    cudaGetSymbolAddress((void**)&ctx3,  g_ctx3);

    const int attn_smem = (BQ * QPAD + BK * KPAD + BK * HD + BQ * BK) * sizeof(float);
    cudaFuncSetAttribute(attn_kernel,
                         cudaFuncAttributeMaxDynamicSharedMemorySize, attn_smem);

    // 0) bf16 hi/lo splits
    int t4x = 4096 * (HIDDEN / 4);
    int t4q = 8192 * (HIDDEN / 4);
    int t4o = 6144 * (HIDDEN / 4);
    split3_kernel<<<(t4x + 255) / 256, 256>>>(x,    a3x,   t4x, 0);
    split3_kernel<<<(t4q + 255) / 256, 256>>>(Wqkv, wqkv3, t4q, 1);
    split3_kernel<<<(t4o + 255) / 256, 256>>>(Wo,   wo3,   t4o, 1);

    // 1) QKV projection: [4096,8192]  (MT=32, NT=64)
    gemm_mma_kernel<<<32 * 64, 256>>>(a3x, wqkv3, qkv, 64, 8192);

    // 2) RoPE
    rope_kernel<<<(4096 * 8 * 7 * 64) / 256, 256>>>(qkv);

    // 3) Flash attention -> ctx fp32
    attn_kernel<<<dim3(32, NH, 2), 256, attn_smem>>>(qkv, ctx);

    // 4) split ctx, output projection: [4096,6144]  (MT=32, NT=48)
    split3_kernel<<<(t4x + 255) / 256, 256>>>(ctx, ctx3, t4x, 0);
    gemm_mma_kernel<<<32 * 48, 256>>>(ctx3, wo3, out, 48, 6144);
}

// round 4
// speedup vs baseline: 2.4238x; 1.5899x over previous
#include <cuda_runtime.h>
#include <cuda_fp16.h>
#include <cuda_bf16.h>
#include <math.h>
#include <stdint.h>

#define S_LEN 2048
#define HIDDEN 6144
#define HD 128
#define NKVH 8
#define NG 6
#define NH 48

// bf16x3 split-K GEMM config
#define K3 (3 * HIDDEN)          // 18432
#define NCH (K3 / 32)            // 576 BK=32 chunks
#define PITCHW 20                // smem row pitch in 32-bit words (40 bf16 = 80B)
#define NSTAGE 4
#define STG_BYTES (128 * PITCHW * 4)           // 10240 per operand
#define STAGE_BYTES (2 * STG_BYTES)            // A + B
#define GEMM_SMEM (NSTAGE * STAGE_BYTES)       // 81920

typedef unsigned int u32;

// ---------------------------------------------------------------------------
// Device scratch
// ---------------------------------------------------------------------------
__device__ float g_qkv[33554432];                 // [2,2048,8,8,128] fp32
__device__ float g_ctx[25165824];                 // [2,2048,48,128]  fp32
__device__ __nv_bfloat16 g_a3x[75497472];         // [4096, 18432]
__device__ __nv_bfloat16 g_wqkv3[150994944];      // [8192, 18432]
__device__ __nv_bfloat16 g_wo3[113246208];        // [6144, 18432]
__device__ __nv_bfloat16 g_ctx3[75497472];        // [4096, 18432]

__device__ __forceinline__ u32 smem_u32(const void* p) {
    u32 a;
    asm("{ .reg .u64 t; cvta.to.shared.u64 t, %1; cvt.u32.u64 %0, t; }" : "=r"(a) : "l"(p));
    return a;
}

#define CP16(d, s) \
    asm volatile("cp.async.cg.shared.global [%0], [%1], 16;" :: "r"(d), "l"(s))
#define CP_COMMIT() asm volatile("cp.async.commit_group;")
#define CP_WAIT(n)  asm volatile("cp.async.wait_group %0;" :: "n"(n))

#define LDSM4(R, addr) \
    asm volatile("ldmatrix.sync.aligned.m8n8.x4.shared.b16 {%0,%1,%2,%3}, [%4];" \
        : "=r"((R)[0]), "=r"((R)[1]), "=r"((R)[2]), "=r"((R)[3]) : "r"(addr))
#define LDSM4T(R, addr) \
    asm volatile("ldmatrix.sync.aligned.m8n8.x4.trans.shared.b16 {%0,%1,%2,%3}, [%4];" \
        : "=r"((R)[0]), "=r"((R)[1]), "=r"((R)[2]), "=r"((R)[3]) : "r"(addr))

__device__ __forceinline__ void mma_bf16(float* c, const u32* a, const u32* b) {
    asm volatile(
        "mma.sync.aligned.m16n8k16.row.col.f32.bf16.bf16.f32 "
        "{%0,%1,%2,%3}, {%4,%5,%6,%7}, {%8,%9}, {%0,%1,%2,%3};"
        : "+f"(c[0]), "+f"(c[1]), "+f"(c[2]), "+f"(c[3])
        : "r"(a[0]), "r"(a[1]), "r"(a[2]), "r"(a[3]), "r"(b[0]), "r"(b[1]));
}
__device__ __forceinline__ void mma_f16(float* c, const u32* a, const u32* b) {
    asm volatile(
        "mma.sync.aligned.m16n8k16.row.col.f32.f16.f16.f32 "
        "{%0,%1,%2,%3}, {%4,%5,%6,%7}, {%8,%9}, {%0,%1,%2,%3};"
        : "+f"(c[0]), "+f"(c[1]), "+f"(c[2]), "+f"(c[3])
        : "r"(a[0]), "r"(a[1]), "r"(a[2]), "r"(a[3]), "r"(b[0]), "r"(b[1]));
}

// ---------------------------------------------------------------------------
// Split fp32 -> bf16 (hi, lo): [hi|hi|lo] (left operand) / [hi|lo|hi] (right)
// ---------------------------------------------------------------------------
__global__ void split3_kernel(const float* __restrict__ in,
                              __nv_bfloat16* __restrict__ out,
                              int total4, int is_right) {
    int idx = blockIdx.x * blockDim.x + threadIdx.x;
    if (idx >= total4) return;
    float4 v = ((const float4*)in)[idx];
    int r = idx / (HIDDEN / 4);
    int c = (idx % (HIDDEN / 4)) * 4;
    float vv[4] = {v.x, v.y, v.z, v.w};
    unsigned hs[4], ls[4];
#pragma unroll
    for (int j = 0; j < 4; j++) {
        __nv_bfloat16 h = __float2bfloat16(vv[j]);
        __nv_bfloat16 l = __float2bfloat16(vv[j] - __bfloat162float(h));
        hs[j] = __bfloat16_as_ushort(h);
        ls[j] = __bfloat16_as_ushort(l);
    }
    uint2 hp = make_uint2(hs[0] | (hs[1] << 16), hs[2] | (hs[3] << 16));
    uint2 lp = make_uint2(ls[0] | (ls[1] << 16), ls[2] | (ls[3] << 16));
    __nv_bfloat16* row = out + (size_t)r * K3 + c;
    *(uint2*)row = hp;
    *(uint2*)(row + HIDDEN)     = is_right ? lp : hp;
    *(uint2*)(row + 2 * HIDDEN) = is_right ? hp : lp;
}

// ---------------------------------------------------------------------------
// bf16 HMMA GEMM: 128x128 tile, BK=32, 4-stage cp.async ring, ldmatrix frags
// ---------------------------------------------------------------------------
__global__ void __launch_bounds__(256, 2)
gemm_mma_kernel(const __nv_bfloat16* __restrict__ A,
                const __nv_bfloat16* __restrict__ B,
                float* __restrict__ C, int NT, int Ntot) {
    extern __shared__ __align__(16) u32 gsm[];
    const u32 gb = smem_u32(gsm);

    const int tid  = threadIdx.x;
    const int lane = tid & 31;
    const int wid  = tid >> 5;
    const int wm   = wid >> 2;          // 0..1
    const int wn   = wid & 3;           // 0..3

    int bid = blockIdx.x;
    int gsz = 8 * NT;
    int g = bid / gsz, r = bid % gsz;
    int mt = g * 8 + (r & 7);
    int nt = r >> 3;
    int bm = mt * 128, bn = nt * 128;

    const int grow = tid >> 2;
    const int gc16 = tid & 3;
    const __nv_bfloat16* Ag = A + (size_t)(bm + grow) * K3 + gc16 * 8;
    const __nv_bfloat16* Bg = B + (size_t)(bn + grow) * K3 + gc16 * 8;
    const u32 doff  = (u32)(grow * PITCHW + gc16 * 4) * 4;
    const u32 doff2 = doff + 64 * PITCHW * 4;

    float acc[4][4][4];
#pragma unroll
    for (int mi = 0; mi < 4; mi++)
#pragma unroll
        for (int ni = 0; ni < 4; ni++)
#pragma unroll
            for (int q = 0; q < 4; q++) acc[mi][ni][q] = 0.f;

    // fragment smem addresses (stage-relative byte offsets)
    const u32 a_off = (u32)((wm * 64 + (lane & 15)) * PITCHW + 4 * (lane >> 4)) * 4;
    const u32 b_off = (u32)((wn * 32 + (lane & 7) + 8 * (lane >> 4)) * PITCHW
                            + 4 * ((lane >> 3) & 1)) * 4;

    // prologue: stages 0..2
#pragma unroll
    for (int s = 0; s < NSTAGE - 1; s++) {
        u32 sA = gb + s * STAGE_BYTES;
        u32 sB = sA + STG_BYTES;
        const __nv_bfloat16* ga = Ag + (size_t)s * 32;
        const __nv_bfloat16* gbp = Bg + (size_t)s * 32;
        CP16(sA + doff,  ga);
        CP16(sA + doff2, ga + (size_t)64 * K3);
        CP16(sB + doff,  gbp);
        CP16(sB + doff2, gbp + (size_t)64 * K3);
        CP_COMMIT();
    }

    for (int c = 0; c < NCH; c++) {
        CP_WAIT(2);
        __syncthreads();
        // prefetch stage c+3 into ring slot (c+3)&3 (== (c-1)&3, free after sync)
        if (c + NSTAGE - 1 < NCH) {
            int s = (c + NSTAGE - 1) & (NSTAGE - 1);
            u32 sA = gb + s * STAGE_BYTES;
            u32 sB = sA + STG_BYTES;
            const __nv_bfloat16* ga = Ag + (size_t)(c + NSTAGE - 1) * 32;
            const __nv_bfloat16* gbp = Bg + (size_t)(c + NSTAGE - 1) * 32;
            CP16(sA + doff,  ga);
            CP16(sA + doff2, ga + (size_t)64 * K3);
            CP16(sB + doff,  gbp);
            CP16(sB + doff2, gbp + (size_t)64 * K3);
        }
        CP_COMMIT();

        u32 stA = gb + (c & (NSTAGE - 1)) * STAGE_BYTES;
        u32 stB = stA + STG_BYTES;
#pragma unroll
        for (int ks = 0; ks < 2; ks++) {
            u32 a[4][4];
#pragma unroll
            for (int mi = 0; mi < 4; mi++)
                LDSM4(a[mi], stA + a_off + mi * (16 * PITCHW * 4) + ks * 32);
#pragma unroll
            for (int np = 0; np < 2; np++) {
                u32 bb[4];
                LDSM4(bb, stB + b_off + np * (16 * PITCHW * 4) + ks * 32);
#pragma unroll
                for (int mi = 0; mi < 4; mi++) {
                    mma_bf16(acc[mi][2 * np],     a[mi], bb);
                    mma_bf16(acc[mi][2 * np + 1], a[mi], bb + 2);
                }
            }
        }
    }

    // epilogue
    const int lr = lane >> 2;
    const int lq = lane & 3;
#pragma unroll
    for (int mi = 0; mi < 4; mi++) {
        int row = bm + wm * 64 + mi * 16 + lr;
#pragma unroll
        for (int ni = 0; ni < 4; ni++) {
            int col = bn + wn * 32 + ni * 8 + lq * 2;
            float* p0 = C + (size_t)row * Ntot + col;
            *(float2*)p0 = make_float2(acc[mi][ni][0], acc[mi][ni][1]);
            *(float2*)(p0 + (size_t)8 * Ntot) = make_float2(acc[mi][ni][2], acc[mi][ni][3]);
        }
    }
}

// ---------------------------------------------------------------------------
// RoPE in-place on q heads (slots 0..5) and k (slot 6)
// ---------------------------------------------------------------------------
__global__ void rope_kernel(float* __restrict__ qkv) {
    int idx = blockIdx.x * blockDim.x + threadIdx.x;
    if (idx >= 4096 * 8 * 7 * 64) return;
    int i = idx & 63;
    int t = idx >> 6;
    int slot = t % 7;
    t /= 7;
    int kvh = t & 7;
    int bs = t >> 3;
    int s = bs & (S_LEN - 1);
    float inv = exp2f(-(float)i * (19.931568569324174f / 64.0f));
    float f = (float)s * inv;
    float c = cosf(f), sn = sinf(f);
    float* p = qkv + (((size_t)bs * NKVH + kvh) * 8 + slot) * HD;
    float a = p[i], b = p[i + 64];
    p[i]      = a * c - b * sn;
    p[i + 64] = b * c + a * sn;
}

// ---------------------------------------------------------------------------
// Flash attention on tensor cores, fp16 hi/lo split (3-term), causal, GQA.
// BQ=128, BK=64, 256 threads; warp w owns rows [16w,16w+16).
// ---------------------------------------------------------------------------
#define QP2 136
#define ATTN_SMEM ((128 * 2 + 64 * 4) * QP2 * 2)   // 139264 bytes

__device__ __forceinline__ u32 pack_h2(float lo, float hi) {
    u32 r;
    asm("cvt.rn.f16x2.f32 %0, %1, %2;" : "=r"(r) : "f"(hi), "f"(lo));
    return r;
}

__global__ void __launch_bounds__(256, 1)
attn_mma_kernel(const float* __restrict__ qkv, float* __restrict__ ctx) {
    extern __shared__ __align__(16) __half hsm[];
    __half* Qh = hsm;
    __half* Ql = Qh + 128 * QP2;
    __half* Kh = Ql + 128 * QP2;
    __half* Kl = Kh + 64 * QP2;
    __half* Vh = Kl + 64 * QP2;
    __half* Vl = Vh + 64 * QP2;

    const int tid  = threadIdx.x;
    const int lane = tid & 31;
    const int wid  = tid >> 5;
    const int qt   = (int)gridDim.x - 1 - blockIdx.x;   // heavy tiles first
    const int h    = blockIdx.y;
    const int b    = blockIdx.z;
    const int kvh  = h / NG, slot = h % NG;
    const int qbase = qt * 128;
    const float scale = 0.08838834764831845f;

    // --- load Q tile (scaled), split hi/lo fp16 ---
#pragma unroll
    for (int it = 0; it < 16; it++) {
        int v = tid + it * 256;
        int row = v >> 5, c4 = v & 31;
        const float* g = qkv + ((((size_t)b * S_LEN + qbase + row) * NKVH + kvh) * 8 + slot) * HD + c4 * 4;
        float4 q = *(const float4*)g;
        float f[4] = {q.x * scale, q.y * scale, q.z * scale, q.w * scale};
        __half hh[4]; float rl[4];
#pragma unroll
        for (int j = 0; j < 4; j++) {
            hh[j] = __float2half_rn(f[j]);
            rl[j] = f[j] - __half2float(hh[j]);
        }
        __half2* dh = (__half2*)&Qh[row * QP2 + c4 * 4];
        dh[0] = __halves2half2(hh[0], hh[1]);
        dh[1] = __halves2half2(hh[2], hh[3]);
        __half2* dl = (__half2*)&Ql[row * QP2 + c4 * 4];
        dl[0] = __halves2half2(__float2half_rn(rl[0]), __float2half_rn(rl[1]));
        dl[1] = __halves2half2(__float2half_rn(rl[2]), __float2half_rn(rl[3]));
    }

    float S[8][4], O[16][4];
    float m0 = -INFINITY, m1 = -INFINITY, l0 = 0.f, l1 = 0.f;
#pragma unroll
    for (int nj = 0; nj < 16; nj++)
#pragma unroll
        for (int q = 0; q < 4; q++) O[nj][q] = 0.f;

    const u32 qh_b = smem_u32(Qh), ql_b = smem_u32(Ql);
    const u32 kh_b = smem_u32(Kh), kl_b = smem_u32(Kl);
    const u32 vh_b = smem_u32(Vh), vl_b = smem_u32(Vl);
    const u32 a_off = ((u32)(wid * 16 + (lane & 15)) * QP2 + 8 * (lane >> 4)) * 2;
    const u32 b_off = ((u32)((lane & 7) + 8 * (lane >> 4)) * QP2 + 8 * ((lane >> 3) & 1)) * 2;
    const u32 v_off = ((u32)((lane & 7) + 8 * ((lane >> 3) & 1)) * QP2 + 8 * (lane >> 4)) * 2;

    const int nkt = 2 * qt + 2;
    for (int kt = 0; kt < nkt; kt++) {
        __syncthreads();
        // --- load K/V tile, split hi/lo ---
#pragma unroll
        for (int it = 0; it < 8; it++) {
            int v = tid + it * 256;
            int row = v >> 5, c4 = v & 31;
            size_t gbse = (((size_t)b * S_LEN + kt * 64 + row) * NKVH + kvh) * 8;
            float4 kk = *(const float4*)(qkv + (gbse + NG) * HD + c4 * 4);
            float4 vv = *(const float4*)(qkv + (gbse + NG + 1) * HD + c4 * 4);
            float fk[4] = {kk.x, kk.y, kk.z, kk.w};
            float fv[4] = {vv.x, vv.y, vv.z, vv.w};
            __half kh4[4], vh4[4]; float krl[4], vrl[4];
#pragma unroll
            for (int j = 0; j < 4; j++) {
                kh4[j] = __float2half_rn(fk[j]); krl[j] = fk[j] - __half2float(kh4[j]);
                vh4[j] = __float2half_rn(fv[j]); vrl[j] = fv[j] - __half2float(vh4[j]);
            }
            int so = row * QP2 + c4 * 4;
            ((__half2*)&Kh[so])[0] = __halves2half2(kh4[0], kh4[1]);
            ((__half2*)&Kh[so])[1] = __halves2half2(kh4[2], kh4[3]);
            ((__half2*)&Kl[so])[0] = __halves2half2(__float2half_rn(krl[0]), __float2half_rn(krl[1]));
            ((__half2*)&Kl[so])[1] = __halves2half2(__float2half_rn(krl[2]), __float2half_rn(krl[3]));
            ((__half2*)&Vh[so])[0] = __halves2half2(vh4[0], vh4[1]);
            ((__half2*)&Vh[so])[1] = __halves2half2(vh4[2], vh4[3]);
            ((__half2*)&Vl[so])[0] = __halves2half2(__float2half_rn(vrl[0]), __float2half_rn(vrl[1]));
            ((__half2*)&Vl[so])[1] = __halves2half2(__float2half_rn(vrl[2]), __float2half_rn(vrl[3]));
        }
        __syncthreads();

        // --- scores S = Q K^T (3-term split) ---
#pragma unroll
        for (int j = 0; j < 8; j++)
#pragma unroll
            for (int q = 0; q < 4; q++) S[j][q] = 0.f;

#pragma unroll
        for (int kc = 0; kc < 8; kc++) {
            u32 ah[4], al[4];
            LDSM4(ah, qh_b + a_off + kc * 32);
            LDSM4(al, ql_b + a_off + kc * 32);
#pragma unroll
            for (int nn = 0; nn < 4; nn++) {
                u32 bh[4], bl[4];
                u32 bo = b_off + nn * (16 * QP2 * 2) + kc * 32;
                LDSM4(bh, kh_b + bo);
                LDSM4(bl, kl_b + bo);
                mma_f16(S[2 * nn],     ah, bh);
                mma_f16(S[2 * nn],     ah, bl);
                mma_f16(S[2 * nn],     al, bh);
                mma_f16(S[2 * nn + 1], ah, bh + 2);
                mma_f16(S[2 * nn + 1], ah, bl + 2);
                mma_f16(S[2 * nn + 1], al, bh + 2);
            }
        }

        // --- causal mask (diagonal tiles only) ---
        if (kt >= 2 * qt) {
            int r0 = qbase + wid * 16 + (lane >> 2);
            int r1 = r0 + 8;
#pragma unroll
            for (int j = 0; j < 8; j++) {
                int c0 = kt * 64 + 8 * j + 2 * (lane & 3);
                if (c0 > r0)     S[j][0] = -1e30f;
                if (c0 + 1 > r0) S[j][1] = -1e30f;
                if (c0 > r1)     S[j][2] = -1e30f;
                if (c0 + 1 > r1) S[j][3] = -1e30f;
            }
        }

        // --- online softmax (rows warp-local, 4 lanes per row) ---
        float rmax0 = -INFINITY, rmax1 = -INFINITY;
#pragma unroll
        for (int j = 0; j < 8; j++) {
            rmax0 = fmaxf(rmax0, fmaxf(S[j][0], S[j][1]));
            rmax1 = fmaxf(rmax1, fmaxf(S[j][2], S[j][3]));
        }
        rmax0 = fmaxf(rmax0, __shfl_xor_sync(0xffffffffu, rmax0, 1));
        rmax0 = fmaxf(rmax0, __shfl_xor_sync(0xffffffffu, rmax0, 2));
        rmax1 = fmaxf(rmax1, __shfl_xor_sync(0xffffffffu, rmax1, 1));
        rmax1 = fmaxf(rmax1, __shfl_xor_sync(0xffffffffu, rmax1, 2));
        float mn0 = fmaxf(m0, rmax0), mn1 = fmaxf(m1, rmax1);
        float al0 = __expf(m0 - mn0), al1 = __expf(m1 - mn1);
        float rs0 = 0.f, rs1 = 0.f;
#pragma unroll
        for (int j = 0; j < 8; j++) {
            S[j][0] = __expf(S[j][0] - mn0);
            S[j][1] = __expf(S[j][1] - mn0);
            S[j][2] = __expf(S[j][2] - mn1);
            S[j][3] = __expf(S[j][3] - mn1);
            rs0 += S[j][0] + S[j][1];
            rs1 += S[j][2] + S[j][3];
        }
        rs0 += __shfl_xor_sync(0xffffffffu, rs0, 1);
        rs0 += __shfl_xor_sync(0xffffffffu, rs0, 2);
        rs1 += __shfl_xor_sync(0xffffffffu, rs1, 1);
        rs1 += __shfl_xor_sync(0xffffffffu, rs1, 2);
        l0 = l0 * al0 + rs0;
        l1 = l1 * al1 + rs1;
        m0 = mn0; m1 = mn1;
#pragma unroll
        for (int nj = 0; nj < 16; nj++) {
            O[nj][0] *= al0; O[nj][1] *= al0;
            O[nj][2] *= al1; O[nj][3] *= al1;
        }

        // --- O += P V (3-term split, P frags built in-register) ---
#pragma unroll
        for (int kc2 = 0; kc2 < 4; kc2++) {
            int j0 = 2 * kc2, j1 = 2 * kc2 + 1;
            u32 pa[4], pl[4];
            // a0:(r0, cols j0), a1:(r1, j0), a2:(r0, j1), a3:(r1, j1)
            float e[4][2] = {{S[j0][0], S[j0][1]}, {S[j0][2], S[j0][3]},
                             {S[j1][0], S[j1][1]}, {S[j1][2], S[j1][3]}};
#pragma unroll
            for (int q = 0; q < 4; q++) {
                __half h0 = __float2half_rn(e[q][0]);
                __half h1 = __float2half_rn(e[q][1]);
                pa[q] = pack_h2(__half2float(h0) * 0.f + (float)__half2float(h0),
                                (float)__half2float(h1));
                // lo remainders
                pl[q] = pack_h2(e[q][0] - __half2float(h0), e[q][1] - __half2float(h1));
            }
#pragma unroll
            for (int nn = 0; nn < 8; nn++) {
                u32 vh[4], vl[4];
                u32 vo = v_off + kc2 * (16 * QP2 * 2) + nn * 32;
                LDSM4T(vh, vh_b + vo);
                LDSM4T(vl, vl_b + vo);
                mma_f16(O[2 * nn],     pa, vh);
                mma_f16(O[2 * nn],     pa, vl);
                mma_f16(O[2 * nn],     pl, vh);
                mma_f16(O[2 * nn + 1], pa, vh + 2);
                mma_f16(O[2 * nn + 1], pa, vl + 2);
                mma_f16(O[2 * nn + 1], pl, vh + 2);
            }
        }
    }

    // --- epilogue: normalize + write ctx[b, s, h, d] ---
    float inv0 = 1.0f / l0, inv1 = 1.0f / l1;
    int r0 = qbase + wid * 16 + (lane >> 2);
    float* d0 = ctx + ((size_t)b * S_LEN + r0) * HIDDEN + h * HD + 2 * (lane & 3);
    float* d1 = d0 + (size_t)8 * HIDDEN;
#pragma unroll
    for (int nj = 0; nj < 16; nj++) {
        *(float2*)(d0 + 8 * nj) = make_float2(O[nj][0] * inv0, O[nj][1] * inv0);
        *(float2*)(d1 + 8 * nj) = make_float2(O[nj][2] * inv1, O[nj][3] * inv1);
    }
}

// ---------------------------------------------------------------------------
extern "C" void kernel_launch(void* const* d_in, const int* in_sizes, int n_in,
                              void* d_out, int out_size) {
    const float* x    = (const float*)d_in[0];   // [2,2048,6144]
    const float* Wqkv = (const float*)d_in[1];   // [8192,6144]
    const float* Wo   = (const float*)d_in[2];   // [6144,6144]
    float* out = (float*)d_out;                  // [2,2048,6144]

    float *qkv = nullptr, *ctx = nullptr;
    __nv_bfloat16 *a3x = nullptr, *wqkv3 = nullptr, *wo3 = nullptr, *ctx3 = nullptr;
    cudaGetSymbolAddress((void**)&qkv,   g_qkv);
    cudaGetSymbolAddress((void**)&ctx,   g_ctx);
    cudaGetSymbolAddress((void**)&a3x,   g_a3x);
    cudaGetSymbolAddress((void**)&wqkv3, g_wqkv3);
    cudaGetSymbolAddress((void**)&wo3,   g_wo3);
    cudaGetSymbolAddress((void**)&ctx3,  g_ctx3);

    cudaFuncSetAttribute(gemm_mma_kernel,
                         cudaFuncAttributeMaxDynamicSharedMemorySize, GEMM_SMEM);
    cudaFuncSetAttribute(attn_mma_kernel,
                         cudaFuncAttributeMaxDynamicSharedMemorySize, ATTN_SMEM);

    // 0) bf16 hi/lo splits
    int t4x = 4096 * (HIDDEN / 4);
    int t4q = 8192 * (HIDDEN / 4);
    int t4o = 6144 * (HIDDEN / 4);
    split3_kernel<<<(t4x + 255) / 256, 256>>>(x,    a3x,   t4x, 0);
    split3_kernel<<<(t4q + 255) / 256, 256>>>(Wqkv, wqkv3, t4q, 1);
    split3_kernel<<<(t4o + 255) / 256, 256>>>(Wo,   wo3,   t4o, 1);

    // 1) QKV projection: [4096,8192]  (MT=32, NT=64)
    gemm_mma_kernel<<<32 * 64, 256, GEMM_SMEM>>>(a3x, wqkv3, qkv, 64, 8192);

    // 2) RoPE
    rope_kernel<<<(4096 * 8 * 7 * 64) / 256, 256>>>(qkv);

    // 3) Flash attention (tensor cores) -> ctx fp32
    attn_mma_kernel<<<dim3(16, NH, 2), 256, ATTN_SMEM>>>(qkv, ctx);

    // 4) split ctx, output projection: [4096,6144]  (MT=32, NT=48)
    split3_kernel<<<(t4x + 255) / 256, 256>>>(ctx, ctx3, t4x, 0);
    gemm_mma_kernel<<<32 * 48, 256, GEMM_SMEM>>>(ctx3, wo3, out, 48, 6144);
}